// round 5
// baseline (speedup 1.0000x reference)
#include <cuda_runtime.h>
#include <cuda_bf16.h>
#include <stdint.h>

// out[B=1024, W=201000] f32 one-hot triple scatter over zeros.
// Inputs: z f32 (unused), hID i32[1024], rID i32[1024], tID i32[1024].
//
// Strategy: TMA bulk-store zeros (memset-equivalent path: full-line writes,
// no SM store pipeline), then per-CTA scalar overwrite of owned hot elements.

#define ENTITIES_N  100000
#define RELATIONS_N 1000
#define WIDTH       201000            // 2E + R (floats per row)
#define BATCH       1024
#define CHUNK_B     16384             // one bulk store = 16 KB
#define CHUNKS_PER_CTA 15
#define SLICE_B     (CHUNK_B * CHUNKS_PER_CTA)      // 245760 B per CTA
#define NBLOCKS     3350              // 3350 * 245760 = 823,296,000 B exact
#define THREADS     128

__global__ void __launch_bounds__(THREADS) tma_onehot_fill(
    const int* __restrict__ hID,
    const int* __restrict__ rID,
    const int* __restrict__ tID,
    float* out)
{
    __shared__ __align__(128) float zbuf[CHUNK_B / 4];   // 16 KB of zeros

    // Cooperatively zero the SMEM staging buffer (float4 stores).
    {
        float4* z4 = reinterpret_cast<float4*>(zbuf);
        const float4 z = make_float4(0.f, 0.f, 0.f, 0.f);
#pragma unroll
        for (int i = 0; i < (CHUNK_B / 16) / THREADS; i++)   // 8 per thread
            z4[i * THREADS + threadIdx.x] = z;
    }
    __syncthreads();

    if (threadIdx.x == 0) {
        // Order generic SMEM writes before async-proxy (TMA) reads.
        asm volatile("fence.proxy.async;" ::: "memory");

        uint32_t saddr;
        asm("{ .reg .u64 t; cvta.to.shared.u64 t, %1; cvt.u32.u64 %0, t; }"
            : "=r"(saddr) : "l"(zbuf));

        char* gbase = reinterpret_cast<char*>(out) +
                      (unsigned long long)blockIdx.x * SLICE_B;
#pragma unroll
        for (int i = 0; i < CHUNKS_PER_CTA; i++) {
            asm volatile(
                "cp.async.bulk.global.shared::cta.bulk_group [%0], [%1], %2;"
                :: "l"(gbase + (size_t)i * CHUNK_B), "r"(saddr), "n"(CHUNK_B)
                : "memory");
        }
        asm volatile("cp.async.bulk.commit_group;" ::: "memory");
        asm volatile("cp.async.bulk.wait_group 0;" ::: "memory");

        // ---- Epilogue: overwrite owned hot elements (<=2 rows, <=6 stores) ----
        const unsigned lo = (unsigned)blockIdx.x * (SLICE_B / 4);  // first float
        const unsigned hi = lo + (SLICE_B / 4);                    // one past last
        const unsigned row0 = lo / (unsigned)WIDTH;
        const unsigned row1 = (hi - 1u) / (unsigned)WIDTH;
        for (unsigned row = row0; row <= row1; row++) {
            const unsigned rbase = row * (unsigned)WIDTH;
            unsigned q0 = rbase + (unsigned)__ldg(&hID[row]);
            unsigned q1 = rbase + (unsigned)(ENTITIES_N + __ldg(&rID[row]));
            unsigned q2 = rbase + (unsigned)(ENTITIES_N + RELATIONS_N +
                                             __ldg(&tID[row]));
            if (q0 >= lo && q0 < hi) out[q0] = 1.0f;
            if (q1 >= lo && q1 < hi) out[q1] = 1.0f;
            if (q2 >= lo && q2 < hi) out[q2] = 1.0f;
        }
    }
}

extern "C" void kernel_launch(void* const* d_in, const int* in_sizes, int n_in,
                              void* d_out, int out_size) {
    const int* hID = (const int*)d_in[1];
    const int* rID = (const int*)d_in[2];
    const int* tID = (const int*)d_in[3];
    tma_onehot_fill<<<NBLOCKS, THREADS>>>(hID, rID, tID, (float*)d_out);
}

// round 6
// speedup vs baseline: 1.1357x; 1.1357x over previous
#include <cuda_runtime.h>
#include <cuda_bf16.h>
#include <stdint.h>

// out[B=1024, W=201000] f32 one-hot triple scatter over zeros.
// Inputs: z f32 (unused), hID i32[1024], rID i32[1024], tID i32[1024].
//
// Fused fill+scatter, 256-bit stores (st.global.v8.f32, sm_100a+).

#define ENTITIES_N  100000
#define RELATIONS_N 1000
#define WIDTH       201000          // floats per row
#define BATCH       1024
#define THREADS     256
#define V8_PER_THR  4               // 4 x 32B per thread
#define V8_PER_BLK  (THREADS * V8_PER_THR)          // 1024 v8 = 32 KB per block
// total v8 chunks = 1024*201000/8 = 25,728,000 = 25125 * 1024 (exact)
#define NBLOCKS     25125

__global__ void __launch_bounds__(THREADS) fused_onehot_fill(
    const int* __restrict__ hID,
    const int* __restrict__ rID,
    const int* __restrict__ tID,
    float* out)
{
    // Thread's first 32B-chunk index; its 4 chunks strided by THREADS.
    const unsigned base = blockIdx.x * (unsigned)V8_PER_BLK + threadIdx.x;

    // ---- Pure fill: 4 x st.global.v8.f32 of zeros ----
    float* p = out + (size_t)base * 8;
#pragma unroll
    for (int k = 0; k < V8_PER_THR; k++) {
        float* addr = p + (size_t)k * (THREADS * 8);
        asm volatile(
            "st.global.v8.f32 [%0], {%1,%1,%1,%1,%1,%1,%1,%1};"
            :: "l"(addr), "f"(0.0f) : "memory");
    }

    // ---- Once-per-thread epilogue: overwrite owned hot elements ----
    // 32-bit math (max flat elem idx 205,823,999 < 2^31).
    const unsigned W8 = WIDTH / 8u;      // 25125 v8 chunks per row (exact)
    const unsigned rowA = base / W8;
    const unsigned rowB = (base + (V8_PER_THR - 1) * THREADS) / W8;

#pragma unroll
    for (int which = 0; which < 2; which++) {
        const unsigned row = which ? rowB : rowA;
        if (which && rowB == rowA) break;

        const unsigned rbase = row * (unsigned)WIDTH;
        unsigned q[3];
        q[0] = rbase + (unsigned)__ldg(&hID[row]);
        q[1] = rbase + (unsigned)(ENTITIES_N + __ldg(&rID[row]));
        q[2] = rbase + (unsigned)(ENTITIES_N + RELATIONS_N + __ldg(&tID[row]));

#pragma unroll
        for (int j = 0; j < 3; j++) {
            const unsigned chunk = q[j] >> 3;          // owning 32B chunk
            const unsigned d     = chunk - base;       // unsigned wrap ok
            if (d < (unsigned)V8_PER_BLK && (d & (THREADS - 1)) == 0u) {
                // Same thread wrote the zeros for this chunk; program order
                // guarantees this 1.0 lands last.
                out[q[j]] = 1.0f;
            }
        }
    }
}

extern "C" void kernel_launch(void* const* d_in, const int* in_sizes, int n_in,
                              void* d_out, int out_size) {
    const int* hID = (const int*)d_in[1];
    const int* rID = (const int*)d_in[2];
    const int* tID = (const int*)d_in[3];
    fused_onehot_fill<<<NBLOCKS, THREADS>>>(hID, rID, tID, (float*)d_out);
}